// round 13
// baseline (speedup 1.0000x reference)
#include <cuda_runtime.h>
#include <stdint.h>

#define N_OBJ 16384
#define N_DIM 4096
#define HB    4096              // stored fine bins; total+ovf > HB -> slow path
#define HW    (HB / 2)          // u32 words per dim (u16-packed pairs)
#define INV_SQRT2 0.70710678118654752440f
#define XCUT  1.1620f           // x < XCUT -> true p >= 0.0502: sentinel sure
#define XC2   1.6433f           // XCUT*sqrt(2): mask test mu >= XC2*v (v>0)

__device__ uint32_t g_hist[(size_t)N_DIM * HW];   // 32 MB, L2-resident
__device__ uint32_t g_ovf[N_DIM];                 // count of j >= HB (rare)

// thr(j) = 0.05f * float32((j+1)/16384)
__device__ __forceinline__ float thr(int j) {
    return __fmul_rn(0.05f, (float)(j + 1) * 6.103515625e-05f);
}

// ---------------- zero: hist + ovf (every launch; graph-safe) -------------
__global__ void zero_kernel() {
    size_t i = (size_t)blockIdx.x * 1024 + threadIdx.x;     // 2048*1024 threads
    ((uint4*)g_hist)[i] = make_uint4(0u, 0u, 0u, 0u);       // 8.4M words exactly
    if (i < N_DIM) g_ovf[i] = 0;
}

// ---------------- phase 1: float4 stream -> FMA mask -> RED hist ----------
// Block 256. Lane owns 4 consecutive dims (float4); warp w owns 2 obj rows.
// Block tile: 128 dims x 16 objects. Grid: (4096/128, 16384/16) = (32, 1024).
__global__ void __launch_bounds__(256) phase1_kernel(
        const float* __restrict__ q_mu, const float* __restrict__ q_var) {
    const int tid = threadIdx.x, lane = tid & 31, wrp = tid >> 5;
    const int dbase = blockIdx.x * 128 + lane * 4;
    const int obj = blockIdx.y * 16 + wrp * 2;

    const float4* mu4  = (const float4*)q_mu;
    const float4* var4 = (const float4*)q_var;
    const size_t a0 = (size_t)obj * (N_DIM / 4) + (dbase >> 2);

    float4 m0 = __ldcs(&mu4[a0]);
    float4 v0 = __ldcs(&var4[a0]);
    float4 m1 = __ldcs(&mu4[a0 + (N_DIM / 4)]);
    float4 v1 = __ldcs(&var4[a0 + (N_DIM / 4)]);

    const float mm[8] = {m0.x, m0.y, m0.z, m0.w, m1.x, m1.y, m1.z, m1.w};
    const float vv[8] = {v0.x, v0.y, v0.z, v0.w, v1.x, v1.y, v1.z, v1.w};

    // Division-free activity mask: mu >= XC2*v  <=>  x >= XCUT (v > 0).
    uint32_t mask = 0;
    #pragma unroll
    for (int r = 0; r < 8; r++)
        if (fmaf(-XC2, vv[r], mm[r]) >= 0.0f) mask |= (1u << r);

    // Full divide+erfc+bin path only for active elements (~1.3 avg/thread).
    while (mask) {
        int r = __ffs(mask) - 1;
        mask &= mask - 1;
        float m = mm[0], v = vv[0];          // select-chain fetch (no spill)
        #pragma unroll
        for (int q = 1; q < 8; q++) {
            m = (r == q) ? mm[q] : m;
            v = (r == q) ? vv[q] : v;
        }
        float xc = __fdividef(m, v) * INV_SQRT2;

        // xc >= ~1.16 > 1: no clamp needed. p = 0.5*erfc(xc).
        float h = xc * xc;                   // exp(-x^2), Dekker-corrected
        float l = fmaf(xc, xc, -h);
        float e = __expf(-h);
        e = fmaf(-l, e, e);
        float den = fmaf(0.3275911f, xc, 1.0f);   // A&S 7.1.26, err<=1.5e-7
        float t = __fdividef(1.0f, den);
        float poly = fmaf(t, 1.061405429f, -1.453152027f);
        poly = fmaf(t, poly, 1.421413741f);
        poly = fmaf(t, poly, -0.284496736f);
        poly = fmaf(t, poly, 0.254829592f);
        float p = 0.5f * t * poly * e;

        if (p <= 0.05f) {                    // thr(16383) == 0.05f exactly
            int j = (int)ceilf(p * 327680.0f) - 1;    // thresholds uniform in p
            j = min(max(j, 0), N_OBJ - 1);
            while (j > 0 && p <= thr(j - 1)) --j;     // fp fixup, ~0-1 iters
            while (j < N_OBJ - 1 && p > thr(j)) ++j;
            const int d = dbase + (r & 3);
            if (j < HB)                       // RED, fire-and-forget
                atomicAdd(&g_hist[(size_t)d * HW + (j >> 1)],
                          1u << ((j & 1) << 4));
            else
                atomicAdd(&g_ovf[d], 1u);     // ~never
        }
    }
}

// ---------------- phase 2: unconditional scan of L2-resident hist ---------
__global__ void __launch_bounds__(1024) phase2_kernel(
        const float* __restrict__ q_mu, const float* __restrict__ q_var,
        float* __restrict__ out) {
    __shared__ uint32_t warp_part[32];
    __shared__ uint32_t red_cnt[32];
    __shared__ int      red_min[32];
    __shared__ uint32_t s_slow[N_OBJ / 2];   // 32 KB, slow path only

    const int tid = threadIdx.x, lane = tid & 31, wid = tid >> 5;
    const int d = blockIdx.x;

    // fast path: 4096-bin scan, 4 bins/thread, coalesced uint2 loads
    const uint32_t* hw = g_hist + (size_t)d * HW + tid * 2;
    uint32_t w0 = hw[0], w1 = hw[1];
    uint32_t b0 = w0 & 0xFFFFu, b1 = w0 >> 16;
    uint32_t b2 = w1 & 0xFFFFu, b3 = w1 >> 16;
    uint32_t s4 = b0 + b1 + b2 + b3;

    uint32_t x = s4;
    #pragma unroll
    for (int o = 1; o < 32; o <<= 1) {
        uint32_t y = __shfl_up_sync(0xffffffffu, x, o);
        if (lane >= o) x += y;
    }
    if (lane == 31) warp_part[wid] = x;
    __syncthreads();
    if (wid == 0) {
        uint32_t ww = warp_part[lane];
        #pragma unroll
        for (int o = 1; o < 32; o <<= 1) {
            uint32_t y = __shfl_up_sync(0xffffffffu, ww, o);
            if (lane >= o) ww += y;
        }
        warp_part[lane] = ww;
    }
    __syncthreads();

    const uint32_t total = warp_part[31];    // C restricted to bins < HB
    uint32_t count = 0;
    int firstj = 0x7fffffff;

    uint32_t cum = x - s4 + (wid > 0 ? warp_part[wid - 1] : 0u);
    int jb = tid * 4;
    cum += b0; if (cum >= (uint32_t)(jb + 1)) { count++; firstj = jb; }
    cum += b1; if (cum >= (uint32_t)(jb + 2)) { count++; firstj = min(firstj, jb + 1); }
    cum += b2; if (cum >= (uint32_t)(jb + 3)) { count++; firstj = min(firstj, jb + 2); }
    cum += b3; if (cum >= (uint32_t)(jb + 4)) { count++; firstj = min(firstj, jb + 3); }

    if (total + g_ovf[d] > (uint32_t)HB) {
        // slow path (C > 4096: >25-sigma event): exact full-range recompute.
        count = 0; firstj = 0x7fffffff;
        for (int k = tid; k < N_OBJ / 2; k += 1024) s_slow[k] = 0;
        __syncthreads();
        for (int k = tid; k < N_OBJ; k += 1024) {
            float m = q_mu[(size_t)k * N_DIM + d];
            float v = q_var[(size_t)k * N_DIM + d];
            if (fmaf(-XC2, v, m) < 0.0f) continue;
            float xc = __fdividef(m, v) * INV_SQRT2;
            float h = xc * xc;
            float l = fmaf(xc, xc, -h);
            float e = __expf(-h);
            e = fmaf(-l, e, e);
            float den = fmaf(0.3275911f, xc, 1.0f);
            float t = __fdividef(1.0f, den);
            float poly = fmaf(t, 1.061405429f, -1.453152027f);
            poly = fmaf(t, poly, 1.421413741f);
            poly = fmaf(t, poly, -0.284496736f);
            poly = fmaf(t, poly, 0.254829592f);
            float p = 0.5f * t * poly * e;
            if (p <= 0.05f) {
                int j = (int)ceilf(p * 327680.0f) - 1;
                j = min(max(j, 0), N_OBJ - 1);
                while (j > 0 && p <= thr(j - 1)) --j;
                while (j < N_OBJ - 1 && p > thr(j)) ++j;
                atomicAdd(&s_slow[j >> 1], 1u << ((j & 1) << 4));
            }
        }
        __syncthreads();
        uint32_t carry = 0;
        for (int c = 0; c < 16; ++c) {
            int j = c * 1024 + tid;
            uint32_t xv = (s_slow[j >> 1] >> ((j & 1) << 4)) & 0xFFFFu;
            #pragma unroll
            for (int o = 1; o < 32; o <<= 1) {
                uint32_t y = __shfl_up_sync(0xffffffffu, xv, o);
                if (lane >= o) xv += y;
            }
            if (lane == 31) warp_part[wid] = xv;
            __syncthreads();
            if (wid == 0) {
                uint32_t ww = warp_part[lane];
                #pragma unroll
                for (int o = 1; o < 32; o <<= 1) {
                    uint32_t y = __shfl_up_sync(0xffffffffu, ww, o);
                    if (lane >= o) ww += y;
                }
                warp_part[lane] = ww;
            }
            __syncthreads();
            uint32_t incl = xv + (wid > 0 ? warp_part[wid - 1] : 0u) + carry;
            if (incl >= (uint32_t)(j + 1)) { count++; firstj = min(firstj, j); }
            __syncthreads();
            carry += warp_part[31];
            __syncthreads();
        }
    }

    // block reduce (sum count, min firstj)
    #pragma unroll
    for (int o = 16; o > 0; o >>= 1) {
        count += __shfl_down_sync(0xffffffffu, count, o);
        firstj = min(firstj, __shfl_down_sync(0xffffffffu, firstj, o));
    }
    if (lane == 0) { red_cnt[wid] = count; red_min[wid] = firstj; }
    __syncthreads();
    if (wid == 0) {
        uint32_t cc = red_cnt[lane];
        int mm = red_min[lane];
        #pragma unroll
        for (int o = 16; o > 0; o >>= 1) {
            cc += __shfl_down_sync(0xffffffffu, cc, o);
            mm = min(mm, __shfl_down_sync(0xffffffffu, mm, o));
        }
        if (lane == 0)
            out[d] = (float)(cc + ((mm == 0x7fffffff) ? 0u : (uint32_t)mm));
    }
}

extern "C" void kernel_launch(void* const* d_in, const int* in_sizes, int n_in,
                              void* d_out, int out_size) {
    const float* q_mu  = (const float*)d_in[0];
    const float* q_var = (const float*)d_in[1];
    float* out = (float*)d_out;

    zero_kernel<<<(N_DIM * HW / 4) / 1024, 1024>>>();        // 2048 blocks
    dim3 g1(N_DIM / 128, N_OBJ / 16);
    phase1_kernel<<<g1, 256>>>(q_mu, q_var);
    phase2_kernel<<<N_DIM, 1024>>>(q_mu, q_var, out);
}

// round 14
// speedup vs baseline: 1.2899x; 1.2899x over previous
#include <cuda_runtime.h>
#include <stdint.h>

#define N_OBJ 16384
#define N_DIM 4096
#define HB    4096              // stored fine bins; C > HB -> exact slow path
#define HW    (HB / 2)          // u32 words per dim (u16-packed pairs)
#define INV_SQRT2 0.70710678118654752440f
#define XCUT  1.1620f           // x < XCUT -> true p >= 0.0502: sentinel sure
#define XC2   1.6433f           // XCUT*sqrt(2): mask test mu >= XC2*v (v>0)

__device__ uint32_t g_hist[(size_t)N_DIM * HW];   // 32 MB, L2-resident
__device__ uint32_t g_cnt[N_DIM];

// thr(j) = 0.05f * float32((j+1)/16384)
__device__ __forceinline__ float thr(int j) {
    return __fmul_rn(0.05f, (float)(j + 1) * 6.103515625e-05f);
}

// ---------------- zero: hist + counts (every launch; graph-safe) ----------
__global__ void zero_kernel() {
    size_t i = (size_t)blockIdx.x * 1024 + threadIdx.x;     // 2048*1024 threads
    ((uint4*)g_hist)[i] = make_uint4(0u, 0u, 0u, 0u);       // 8.4M words exactly
    if (i < N_DIM) g_cnt[i] = 0;
}

// ---------------- phase 1: FMA mask -> warp compaction -> RED hist --------
// R12 layout: block 256 = (32 tx=dim, 8 ty=obj), 8 objs/thread.
// Tile 32 dims x 64 objs. Grid (128, 256).
__global__ void __launch_bounds__(256) phase1_kernel(
        const float* __restrict__ q_mu, const float* __restrict__ q_var) {
    __shared__ uint32_t s_cnt[32];
    __shared__ float   qm[8 * 256];          // per-warp queues (worst case 256)
    __shared__ float   qv[8 * 256];
    __shared__ uint8_t qx[8 * 256];

    const int tid = threadIdx.x, tx = tid & 31, ty = tid >> 5;
    const int dB = blockIdx.x * 32;
    const int d = dB + tx;
    const size_t base = (size_t)(blockIdx.y * 64 + ty) * N_DIM + d;
    const int wq = ty * 256;

    if (tid < 32) s_cnt[tid] = 0;
    __syncthreads();

    float mm[8], vv[8];
    #pragma unroll
    for (int r = 0; r < 8; r++) {
        mm[r] = __ldcs(q_mu  + base + (size_t)(r * 8) * N_DIM);
        vv[r] = __ldcs(q_var + base + (size_t)(r * 8) * N_DIM);
    }

    // Division-free activity mask: mu >= XC2*v  <=>  x >= XCUT (v > 0).
    // Skipped elements have true p >= 0.0502 (margin 1.6e-4 >> 1.5e-7 approx
    // error): sentinel guaranteed -> active set identical to full evaluation.
    uint32_t mask = 0;
    #pragma unroll
    for (int r = 0; r < 8; r++)
        if (fmaf(-XC2, vv[r], mm[r]) >= 0.0f) mask |= (1u << r);

    // Warp-exclusive prefix of active counts -> queue slots.
    int na = __popc(mask);
    int pre = na;
    #pragma unroll
    for (int o = 1; o < 32; o <<= 1) {
        int y = __shfl_up_sync(0xffffffffu, pre, o);
        if (tx >= o) pre += y;
    }
    const int nq = __shfl_sync(0xffffffffu, pre, 31);
    int k = wq + (pre - na);

    // Push actives with constant-index (unrolled) register reads.
    #pragma unroll
    for (int r = 0; r < 8; r++) {
        if ((mask >> r) & 1u) {
            qm[k] = mm[r]; qv[k] = vv[r]; qx[k] = (uint8_t)tx; k++;
        }
    }
    __syncwarp();

    // Drain: ceil(nq/32) body executions per lane (warp-mean, not warp-max).
    for (int i = (int)tx; i < nq; i += 32) {
        float m = qm[wq + i], v = qv[wq + i];
        int   dtx = qx[wq + i];
        float xc = __fdividef(m, v) * INV_SQRT2;

        // xc >= ~1.16 > 1: no clamp needed. p = 0.5*erfc(xc).
        float h = xc * xc;                   // exp(-x^2), Dekker-corrected
        float l = fmaf(xc, xc, -h);
        float e = __expf(-h);
        e = fmaf(-l, e, e);
        float den = fmaf(0.3275911f, xc, 1.0f);   // A&S 7.1.26, err<=1.5e-7
        float t = __fdividef(1.0f, den);
        float poly = fmaf(t, 1.061405429f, -1.453152027f);
        poly = fmaf(t, poly, 1.421413741f);
        poly = fmaf(t, poly, -0.284496736f);
        poly = fmaf(t, poly, 0.254829592f);
        float p = 0.5f * t * poly * e;

        if (p <= 0.05f) {                    // thr(16383) == 0.05f exactly
            int j = (int)ceilf(p * 327680.0f) - 1;    // thresholds uniform in p
            j = min(max(j, 0), N_OBJ - 1);
            while (j > 0 && p <= thr(j - 1)) --j;     // fp fixup, ~0-1 iters
            while (j < N_OBJ - 1 && p > thr(j)) ++j;
            atomicAdd(&s_cnt[dtx], 1u);
            if (j < HB)                       // RED, fire-and-forget
                atomicAdd(&g_hist[(size_t)(dB + dtx) * HW + (j >> 1)],
                          1u << ((j & 1) << 4));
        }
    }

    __syncthreads();
    if (tid < 32 && s_cnt[tid])
        atomicAdd(&g_cnt[dB + tid], s_cnt[tid]);      // RED
}

// ---------------- phase 2: read-only scan of L2-resident hist (R12) -------
__global__ void __launch_bounds__(1024) phase2_kernel(
        const float* __restrict__ q_mu, const float* __restrict__ q_var,
        float* __restrict__ out) {
    __shared__ uint32_t warp_part[32];
    __shared__ uint32_t red_cnt[32];
    __shared__ int      red_min[32];
    __shared__ uint32_t s_slow[N_OBJ / 2];   // 32 KB, slow path only

    const int tid = threadIdx.x, lane = tid & 31, wid = tid >> 5;
    const int d = blockIdx.x;
    const uint32_t C = g_cnt[d];

    if (C == 0) { if (tid == 0) out[d] = 0.0f; return; }

    uint32_t count = 0;
    int firstj = 0x7fffffff;

    if (C <= (uint32_t)HB) {
        // fast path: single 4096-bin scan, 4 bins/thread, coalesced
        const uint32_t* hw = g_hist + (size_t)d * HW + tid * 2;
        uint32_t w0 = hw[0], w1 = hw[1];
        uint32_t b0 = w0 & 0xFFFFu, b1 = w0 >> 16;
        uint32_t b2 = w1 & 0xFFFFu, b3 = w1 >> 16;
        uint32_t s4 = b0 + b1 + b2 + b3;

        uint32_t x = s4;
        #pragma unroll
        for (int o = 1; o < 32; o <<= 1) {
            uint32_t y = __shfl_up_sync(0xffffffffu, x, o);
            if (lane >= o) x += y;
        }
        if (lane == 31) warp_part[wid] = x;
        __syncthreads();
        if (wid == 0) {
            uint32_t ww = warp_part[lane];
            #pragma unroll
            for (int o = 1; o < 32; o <<= 1) {
                uint32_t y = __shfl_up_sync(0xffffffffu, ww, o);
                if (lane >= o) ww += y;
            }
            warp_part[lane] = ww;
        }
        __syncthreads();

        uint32_t cum = x - s4 + (wid > 0 ? warp_part[wid - 1] : 0u);
        int jb = tid * 4;
        cum += b0; if (cum >= (uint32_t)(jb + 1)) { count++; firstj = jb; }
        cum += b1; if (cum >= (uint32_t)(jb + 2)) { count++; firstj = min(firstj, jb + 1); }
        cum += b2; if (cum >= (uint32_t)(jb + 3)) { count++; firstj = min(firstj, jb + 2); }
        cum += b3; if (cum >= (uint32_t)(jb + 4)) { count++; firstj = min(firstj, jb + 3); }
    } else {
        // slow path (C > 4096: >25-sigma event): exact full-range recompute.
        for (int k = tid; k < N_OBJ / 2; k += 1024) s_slow[k] = 0;
        __syncthreads();
        for (int k = tid; k < N_OBJ; k += 1024) {
            float m = q_mu[(size_t)k * N_DIM + d];
            float v = q_var[(size_t)k * N_DIM + d];
            if (fmaf(-XC2, v, m) < 0.0f) continue;
            float xc = __fdividef(m, v) * INV_SQRT2;
            float h = xc * xc;
            float l = fmaf(xc, xc, -h);
            float e = __expf(-h);
            e = fmaf(-l, e, e);
            float den = fmaf(0.3275911f, xc, 1.0f);
            float t = __fdividef(1.0f, den);
            float poly = fmaf(t, 1.061405429f, -1.453152027f);
            poly = fmaf(t, poly, 1.421413741f);
            poly = fmaf(t, poly, -0.284496736f);
            poly = fmaf(t, poly, 0.254829592f);
            float p = 0.5f * t * poly * e;
            if (p <= 0.05f) {
                int j = (int)ceilf(p * 327680.0f) - 1;
                j = min(max(j, 0), N_OBJ - 1);
                while (j > 0 && p <= thr(j - 1)) --j;
                while (j < N_OBJ - 1 && p > thr(j)) ++j;
                atomicAdd(&s_slow[j >> 1], 1u << ((j & 1) << 4));
            }
        }
        __syncthreads();
        uint32_t carry = 0;
        for (int c = 0; c < 16; ++c) {
            int j = c * 1024 + tid;
            uint32_t xv = (s_slow[j >> 1] >> ((j & 1) << 4)) & 0xFFFFu;
            #pragma unroll
            for (int o = 1; o < 32; o <<= 1) {
                uint32_t y = __shfl_up_sync(0xffffffffu, xv, o);
                if (lane >= o) xv += y;
            }
            if (lane == 31) warp_part[wid] = xv;
            __syncthreads();
            if (wid == 0) {
                uint32_t ww = warp_part[lane];
                #pragma unroll
                for (int o = 1; o < 32; o <<= 1) {
                    uint32_t y = __shfl_up_sync(0xffffffffu, ww, o);
                    if (lane >= o) ww += y;
                }
                warp_part[lane] = ww;
            }
            __syncthreads();
            uint32_t incl = xv + (wid > 0 ? warp_part[wid - 1] : 0u) + carry;
            if (incl >= (uint32_t)(j + 1)) { count++; firstj = min(firstj, j); }
            __syncthreads();
            carry += warp_part[31];
            __syncthreads();
        }
    }

    // block reduce (sum count, min firstj)
    #pragma unroll
    for (int o = 16; o > 0; o >>= 1) {
        count += __shfl_down_sync(0xffffffffu, count, o);
        firstj = min(firstj, __shfl_down_sync(0xffffffffu, firstj, o));
    }
    if (lane == 0) { red_cnt[wid] = count; red_min[wid] = firstj; }
    __syncthreads();
    if (wid == 0) {
        uint32_t cc = red_cnt[lane];
        int mm = red_min[lane];
        #pragma unroll
        for (int o = 16; o > 0; o >>= 1) {
            cc += __shfl_down_sync(0xffffffffu, cc, o);
            mm = min(mm, __shfl_down_sync(0xffffffffu, mm, o));
        }
        if (lane == 0)
            out[d] = (float)(cc + ((mm == 0x7fffffff) ? 0u : (uint32_t)mm));
    }
}

extern "C" void kernel_launch(void* const* d_in, const int* in_sizes, int n_in,
                              void* d_out, int out_size) {
    const float* q_mu  = (const float*)d_in[0];
    const float* q_var = (const float*)d_in[1];
    float* out = (float*)d_out;

    zero_kernel<<<(N_DIM * HW / 4) / 1024, 1024>>>();        // 2048 blocks
    dim3 g1(N_DIM / 32, N_OBJ / 64);
    phase1_kernel<<<g1, 256>>>(q_mu, q_var);
    phase2_kernel<<<N_DIM, 1024>>>(q_mu, q_var, out);
}

// round 15
// speedup vs baseline: 1.3460x; 1.0435x over previous
#include <cuda_runtime.h>
#include <stdint.h>

#define N_OBJ 16384
#define N_DIM 4096
#define HB    4096              // stored fine bins; C > HB -> exact slow path
#define HW    (HB / 2)          // u32 words per dim (u16-packed pairs)
#define INV_SQRT2 0.70710678118654752440f
#define XCUT  1.1620f           // x < XCUT -> true p >= 0.0502: sentinel sure
#define XC2   1.6433f           // XCUT*sqrt(2): mask test mu >= XC2*v (v>0)

__device__ uint32_t g_hist[(size_t)N_DIM * HW];   // 32 MB, L2-resident
__device__ uint32_t g_cnt[N_DIM];

// thr(j) = 0.05f * float32((j+1)/16384)
__device__ __forceinline__ float thr(int j) {
    return __fmul_rn(0.05f, (float)(j + 1) * 6.103515625e-05f);
}

// ---------------- zero: hist + counts (every launch; graph-safe) ----------
__global__ void zero_kernel() {
    size_t i = (size_t)blockIdx.x * 1024 + threadIdx.x;     // 2048*1024 threads
    ((uint4*)g_hist)[i] = make_uint4(0u, 0u, 0u, 0u);       // 8.4M words exactly
    if (i < N_DIM) g_cnt[i] = 0;
}

// ---------------- phase 1: LDG.128 -> FMA mask -> warp queue -> RED -------
// Block 256 = 8 warps. Lane owns 4 consecutive dims (float4) x 2 objects.
// Block tile: 128 dims x 16 objs. Grid (4096/128, 16384/16) = (32, 1024).
__global__ void __launch_bounds__(256) phase1_kernel(
        const float* __restrict__ q_mu, const float* __restrict__ q_var) {
    __shared__ uint32_t s_cnt[128];
    __shared__ float2  qmv[8 * 256];         // per-warp queues (worst case 256)
    __shared__ uint8_t qx[8 * 256];

    const int tid = threadIdx.x, lane = tid & 31, wrp = tid >> 5;
    const int dB = blockIdx.x * 128;
    const int obj = blockIdx.y * 16 + wrp * 2;
    const int wq = wrp * 256;

    for (int k = tid; k < 128; k += 256) s_cnt[k] = 0;
    __syncthreads();

    const float4* mu4  = (const float4*)q_mu;
    const float4* var4 = (const float4*)q_var;
    const size_t a0 = (size_t)obj * (N_DIM / 4) + (dB >> 2) + lane;

    float4 m0 = __ldcs(&mu4[a0]);
    float4 v0 = __ldcs(&var4[a0]);
    float4 m1 = __ldcs(&mu4[a0 + (N_DIM / 4)]);
    float4 v1 = __ldcs(&var4[a0 + (N_DIM / 4)]);

    const float mm[8] = {m0.x, m0.y, m0.z, m0.w, m1.x, m1.y, m1.z, m1.w};
    const float vv[8] = {v0.x, v0.y, v0.z, v0.w, v1.x, v1.y, v1.z, v1.w};

    // Division-free activity mask: mu >= XC2*v  <=>  x >= XCUT (v > 0).
    // Skipped elements have true p >= 0.0502 (margin 1.6e-4 >> 1.5e-7 approx
    // error): sentinel guaranteed -> active set identical to full evaluation.
    uint32_t mask = 0;
    #pragma unroll
    for (int r = 0; r < 8; r++)
        if (fmaf(-XC2, vv[r], mm[r]) >= 0.0f) mask |= (1u << r);

    // Warp-exclusive prefix of active counts -> queue slots.
    int na = __popc(mask);
    int pre = na;
    #pragma unroll
    for (int o = 1; o < 32; o <<= 1) {
        int y = __shfl_up_sync(0xffffffffu, pre, o);
        if (lane >= o) pre += y;
    }
    const int nq = __shfl_sync(0xffffffffu, pre, 31);
    int k = wq + (pre - na);

    // Push actives: one STS.64 (m,v) + one STS.8 (dim-in-block) each.
    #pragma unroll
    for (int r = 0; r < 8; r++) {
        if ((mask >> r) & 1u) {
            qmv[k] = make_float2(mm[r], vv[r]);
            qx[k] = (uint8_t)(lane * 4 + (r & 3));
            k++;
        }
    }
    __syncwarp();

    // Drain: ceil(nq/32) body executions per lane (warp-mean, not warp-max).
    for (int i = lane; i < nq; i += 32) {
        float2 mv = qmv[wq + i];
        int dloc = qx[wq + i];
        float xc = __fdividef(mv.x, mv.y) * INV_SQRT2;

        // xc >= ~1.16 > 1: no clamp needed. p = 0.5*erfc(xc).
        float h = xc * xc;                   // exp(-x^2), Dekker-corrected
        float l = fmaf(xc, xc, -h);
        float e = __expf(-h);
        e = fmaf(-l, e, e);
        float den = fmaf(0.3275911f, xc, 1.0f);   // A&S 7.1.26, err<=1.5e-7
        float t = __fdividef(1.0f, den);
        float poly = fmaf(t, 1.061405429f, -1.453152027f);
        poly = fmaf(t, poly, 1.421413741f);
        poly = fmaf(t, poly, -0.284496736f);
        poly = fmaf(t, poly, 0.254829592f);
        float p = 0.5f * t * poly * e;

        if (p <= 0.05f) {                    // thr(16383) == 0.05f exactly
            int j = (int)ceilf(p * 327680.0f) - 1;    // thresholds uniform in p
            j = min(max(j, 0), N_OBJ - 1);
            while (j > 0 && p <= thr(j - 1)) --j;     // fp fixup, ~0-1 iters
            while (j < N_OBJ - 1 && p > thr(j)) ++j;
            atomicAdd(&s_cnt[dloc], 1u);
            if (j < HB)                       // RED, fire-and-forget
                atomicAdd(&g_hist[(size_t)(dB + dloc) * HW + (j >> 1)],
                          1u << ((j & 1) << 4));
        }
    }

    __syncthreads();
    for (int k2 = tid; k2 < 128; k2 += 256)
        if (s_cnt[k2]) atomicAdd(&g_cnt[dB + k2], s_cnt[k2]);    // RED
}

// ---------------- phase 2: read-only scan of L2-resident hist (R12) -------
__global__ void __launch_bounds__(1024) phase2_kernel(
        const float* __restrict__ q_mu, const float* __restrict__ q_var,
        float* __restrict__ out) {
    __shared__ uint32_t warp_part[32];
    __shared__ uint32_t red_cnt[32];
    __shared__ int      red_min[32];
    __shared__ uint32_t s_slow[N_OBJ / 2];   // 32 KB, slow path only

    const int tid = threadIdx.x, lane = tid & 31, wid = tid >> 5;
    const int d = blockIdx.x;
    const uint32_t C = g_cnt[d];

    if (C == 0) { if (tid == 0) out[d] = 0.0f; return; }

    uint32_t count = 0;
    int firstj = 0x7fffffff;

    if (C <= (uint32_t)HB) {
        // fast path: single 4096-bin scan, 4 bins/thread, coalesced
        const uint32_t* hw = g_hist + (size_t)d * HW + tid * 2;
        uint32_t w0 = hw[0], w1 = hw[1];
        uint32_t b0 = w0 & 0xFFFFu, b1 = w0 >> 16;
        uint32_t b2 = w1 & 0xFFFFu, b3 = w1 >> 16;
        uint32_t s4 = b0 + b1 + b2 + b3;

        uint32_t x = s4;
        #pragma unroll
        for (int o = 1; o < 32; o <<= 1) {
            uint32_t y = __shfl_up_sync(0xffffffffu, x, o);
            if (lane >= o) x += y;
        }
        if (lane == 31) warp_part[wid] = x;
        __syncthreads();
        if (wid == 0) {
            uint32_t ww = warp_part[lane];
            #pragma unroll
            for (int o = 1; o < 32; o <<= 1) {
                uint32_t y = __shfl_up_sync(0xffffffffu, ww, o);
                if (lane >= o) ww += y;
            }
            warp_part[lane] = ww;
        }
        __syncthreads();

        uint32_t cum = x - s4 + (wid > 0 ? warp_part[wid - 1] : 0u);
        int jb = tid * 4;
        cum += b0; if (cum >= (uint32_t)(jb + 1)) { count++; firstj = jb; }
        cum += b1; if (cum >= (uint32_t)(jb + 2)) { count++; firstj = min(firstj, jb + 1); }
        cum += b2; if (cum >= (uint32_t)(jb + 3)) { count++; firstj = min(firstj, jb + 2); }
        cum += b3; if (cum >= (uint32_t)(jb + 4)) { count++; firstj = min(firstj, jb + 3); }
    } else {
        // slow path (C > 4096: >25-sigma event): exact full-range recompute.
        for (int k = tid; k < N_OBJ / 2; k += 1024) s_slow[k] = 0;
        __syncthreads();
        for (int k = tid; k < N_OBJ; k += 1024) {
            float m = q_mu[(size_t)k * N_DIM + d];
            float v = q_var[(size_t)k * N_DIM + d];
            if (fmaf(-XC2, v, m) < 0.0f) continue;
            float xc = __fdividef(m, v) * INV_SQRT2;
            float h = xc * xc;
            float l = fmaf(xc, xc, -h);
            float e = __expf(-h);
            e = fmaf(-l, e, e);
            float den = fmaf(0.3275911f, xc, 1.0f);
            float t = __fdividef(1.0f, den);
            float poly = fmaf(t, 1.061405429f, -1.453152027f);
            poly = fmaf(t, poly, 1.421413741f);
            poly = fmaf(t, poly, -0.284496736f);
            poly = fmaf(t, poly, 0.254829592f);
            float p = 0.5f * t * poly * e;
            if (p <= 0.05f) {
                int j = (int)ceilf(p * 327680.0f) - 1;
                j = min(max(j, 0), N_OBJ - 1);
                while (j > 0 && p <= thr(j - 1)) --j;
                while (j < N_OBJ - 1 && p > thr(j)) ++j;
                atomicAdd(&s_slow[j >> 1], 1u << ((j & 1) << 4));
            }
        }
        __syncthreads();
        uint32_t carry = 0;
        for (int c = 0; c < 16; ++c) {
            int j = c * 1024 + tid;
            uint32_t xv = (s_slow[j >> 1] >> ((j & 1) << 4)) & 0xFFFFu;
            #pragma unroll
            for (int o = 1; o < 32; o <<= 1) {
                uint32_t y = __shfl_up_sync(0xffffffffu, xv, o);
                if (lane >= o) xv += y;
            }
            if (lane == 31) warp_part[wid] = xv;
            __syncthreads();
            if (wid == 0) {
                uint32_t ww = warp_part[lane];
                #pragma unroll
                for (int o = 1; o < 32; o <<= 1) {
                    uint32_t y = __shfl_up_sync(0xffffffffu, ww, o);
                    if (lane >= o) ww += y;
                }
                warp_part[lane] = ww;
            }
            __syncthreads();
            uint32_t incl = xv + (wid > 0 ? warp_part[wid - 1] : 0u) + carry;
            if (incl >= (uint32_t)(j + 1)) { count++; firstj = min(firstj, j); }
            __syncthreads();
            carry += warp_part[31];
            __syncthreads();
        }
    }

    // block reduce (sum count, min firstj)
    #pragma unroll
    for (int o = 16; o > 0; o >>= 1) {
        count += __shfl_down_sync(0xffffffffu, count, o);
        firstj = min(firstj, __shfl_down_sync(0xffffffffu, firstj, o));
    }
    if (lane == 0) { red_cnt[wid] = count; red_min[wid] = firstj; }
    __syncthreads();
    if (wid == 0) {
        uint32_t cc = red_cnt[lane];
        int mm = red_min[lane];
        #pragma unroll
        for (int o = 16; o > 0; o >>= 1) {
            cc += __shfl_down_sync(0xffffffffu, cc, o);
            mm = min(mm, __shfl_down_sync(0xffffffffu, mm, o));
        }
        if (lane == 0)
            out[d] = (float)(cc + ((mm == 0x7fffffff) ? 0u : (uint32_t)mm));
    }
}

extern "C" void kernel_launch(void* const* d_in, const int* in_sizes, int n_in,
                              void* d_out, int out_size) {
    const float* q_mu  = (const float*)d_in[0];
    const float* q_var = (const float*)d_in[1];
    float* out = (float*)d_out;

    zero_kernel<<<(N_DIM * HW / 4) / 1024, 1024>>>();        // 2048 blocks
    dim3 g1(N_DIM / 128, N_OBJ / 16);
    phase1_kernel<<<g1, 256>>>(q_mu, q_var);
    phase2_kernel<<<N_DIM, 1024>>>(q_mu, q_var, out);
}